// round 1
// baseline (speedup 1.0000x reference)
#include <cuda_runtime.h>
#include <math.h>

#define N_TOK 2048
#define NROWS 16384   // N_TOK * 8 codebook-groups
#define KCB   16384   // codebook entries

// Scratch (no allocs allowed): ~8MB feature matrices + small buffers
__device__ float g_At[64 * NROWS];   // [d'][n]: d'<32 -> 0.5*(1-inv_var), d'>=32 -> mu*inv_var
__device__ float g_CBt[64 * KCB];    // [d'][k]: d'<32 -> c^2, d'>=32 -> c
__device__ float g_klpart[N_TOK];
__device__ int   g_idx[NROWS];

// ---------------------------------------------------------------- prep
__global__ void prep_kernel(const float* __restrict__ z) {
    int t = blockIdx.x;       // 2048 tokens
    int j = threadIdx.x;      // 256 features
    float mu = z[t * 512 + j];
    float lv = z[t * 512 + 256 + j];
    lv = fminf(fmaxf(lv, -30.0f), 20.0f);
    float var = expf(lv);
    float inv_var = 1.0f / var;
    int d = j >> 3, c = j & 7;
    int n = t * 8 + c;
    g_At[d * NROWS + n]        = 0.5f * (1.0f - inv_var);
    g_At[(d + 32) * NROWS + n] = mu * inv_var;

    // kl partial (coefficients ge/eq/le always sum to 1)
    float e = mu * mu + var - 1.0f - lv;
    __shared__ float red[256];
    red[j] = e;
    __syncthreads();
    for (int s = 128; s > 0; s >>= 1) {
        if (j < s) red[j] += red[j + s];
        __syncthreads();
    }
    if (j == 0) g_klpart[t] = red[0];
}

__global__ void cb_kernel(const float* __restrict__ cb) {
    int i = blockIdx.x * 256 + threadIdx.x;   // 524288
    if (i >= KCB * 32) return;
    int k = i >> 5, d = i & 31;
    float v = cb[i];
    g_CBt[d * KCB + k]        = v * v;
    g_CBt[(d + 32) * KCB + k] = v;
}

// ---------------------------------------------------------------- GEMM + argmax
__device__ __forceinline__ void cp16(unsigned dst, const void* src) {
    asm volatile("cp.async.cg.shared.global [%0], [%1], 16;\n" :: "r"(dst), "l"(src));
}
__device__ __forceinline__ void fma2(unsigned long long& d, unsigned long long a, unsigned long long b) {
    asm("fma.rn.f32x2 %0, %1, %2, %3;" : "=l"(d) : "l"(a), "l"(b), "l"(d));
}

// 256 threads (16x16). BN=128 rows, BK=128 codebook entries per tile, D=64.
// A-tile duplicated in smem so LDS.128 yields (a,a) f32x2 broadcast pairs.
__global__ __launch_bounds__(256, 1) void vq_kernel() {
    extern __shared__ float smem[];
    float* sA = smem;             // [64][256] duplicated  (64KB)
    float* sB = smem + 64 * 256;  // [2][64][128] double-buffered (64KB)
    int tid = threadIdx.x;
    int tx = tid & 15, ty = tid >> 4;
    int n0 = blockIdx.x * 128;
    unsigned sB_base = (unsigned)__cvta_generic_to_shared(sB);

    // Load + duplicate A tile (once per CTA)
    for (int r = tid; r < 8192; r += 256) {
        int d = r >> 7, i = r & 127;
        float v = g_At[d * NROWS + n0 + i];
        sA[d * 256 + 2 * i]     = v;
        sA[d * 256 + 2 * i + 1] = v;
    }

    // Prefetch B tile 0
    for (int r = tid; r < 2048; r += 256) {
        int d = r >> 5, q = (r & 31) * 4;
        cp16(sB_base + (unsigned)(d * 128 + q) * 4u, g_CBt + d * KCB + q);
    }
    asm volatile("cp.async.commit_group;\n" ::: "memory");

    float mx[8];
    int bi[8];
#pragma unroll
    for (int r = 0; r < 8; r++) { mx[r] = -INFINITY; bi[r] = 0; }

    for (int kt = 0; kt < 128; kt++) {
        if (kt + 1 < 128) {
            unsigned dstb = sB_base + (unsigned)(((kt + 1) & 1) * 8192) * 4u;
            const float* srcb = g_CBt + (kt + 1) * 128;
            for (int r = tid; r < 2048; r += 256) {
                int d = r >> 5, q = (r & 31) * 4;
                cp16(dstb + (unsigned)(d * 128 + q) * 4u, srcb + d * KCB + q);
            }
            asm volatile("cp.async.commit_group;\n" ::: "memory");
            asm volatile("cp.async.wait_group 1;\n" ::: "memory");
        } else {
            asm volatile("cp.async.wait_group 0;\n" ::: "memory");
        }
        __syncthreads();
        const float* Bb = sB + (kt & 1) * 8192;

        unsigned long long acc[8][4];
#pragma unroll
        for (int r = 0; r < 8; r++)
#pragma unroll
            for (int p = 0; p < 4; p++) acc[r][p] = 0ULL;

#pragma unroll 8
        for (int d = 0; d < 64; d++) {
            const ulonglong2* pa = (const ulonglong2*)(sA + d * 256 + ty * 16);
            ulonglong2 A0 = pa[0], A1 = pa[1], A2 = pa[2], A3 = pa[3];
            ulonglong2 B0 = *(const ulonglong2*)(Bb + d * 128 + tx * 4);
            ulonglong2 B1 = *(const ulonglong2*)(Bb + d * 128 + 64 + tx * 4);
            unsigned long long av[8] = {A0.x, A0.y, A1.x, A1.y, A2.x, A2.y, A3.x, A3.y};
            unsigned long long bv[4] = {B0.x, B0.y, B1.x, B1.y};
#pragma unroll
            for (int r = 0; r < 8; r++)
#pragma unroll
                for (int p = 0; p < 4; p++)
                    fma2(acc[r][p], av[r], bv[p]);
        }

        // per-tile running argmax (within-thread scan is ascending k)
        int kbase = kt * 128;
#pragma unroll
        for (int r = 0; r < 8; r++) {
#pragma unroll
            for (int p = 0; p < 4; p++) {
                float lo, hi;
                asm("mov.b64 {%0, %1}, %2;" : "=f"(lo), "=f"(hi) : "l"(acc[r][p]));
                int kk = kbase + ((p & 2) ? 64 : 0) + tx * 4 + ((p & 1) ? 2 : 0);
                if (lo > mx[r]) { mx[r] = lo; bi[r] = kk; }
                if (hi > mx[r]) { mx[r] = hi; bi[r] = kk + 1; }
            }
        }
        __syncthreads();   // before overwriting the buffer we just computed
    }

    // reduce argmax across the 16 tx-lanes sharing each row (tie -> lowest k)
#pragma unroll
    for (int r = 0; r < 8; r++) {
        float m = mx[r];
        int b = bi[r];
#pragma unroll
        for (int off = 8; off > 0; off >>= 1) {
            float om = __shfl_xor_sync(0xffffffffu, m, off, 16);
            int ob = __shfl_xor_sync(0xffffffffu, b, off, 16);
            if (om > m || (om == m && ob < b)) { m = om; b = ob; }
        }
        if (tx == 0) g_idx[n0 + ty * 8 + r] = b;
    }
}

// ---------------------------------------------------------------- outputs
__global__ void gather_kernel(const float* __restrict__ cb, float* __restrict__ out) {
    int i = blockIdx.x * 256 + threadIdx.x;   // 524288 zhat elements
    if (i >= N_TOK * 256) return;
    int j = i & 255;
    int t = i >> 8;
    int idx = g_idx[t * 8 + (j & 7)];
    out[i] = cb[idx * 32 + (j >> 3)];          // zhat[t, d*8+c] = codebook[idx[t,c], d]
}

__global__ void final_small(float* __restrict__ out) {
    if (blockIdx.x == 0) {
        __shared__ float red[256];
        int j = threadIdx.x;
        float s = 0.0f;
        for (int i = j; i < N_TOK; i += 256) s += g_klpart[i];
        red[j] = s;
        __syncthreads();
        for (int st = 128; st > 0; st >>= 1) {
            if (j < st) red[j] += red[j + st];
            __syncthreads();
        }
        if (j == 0) out[524288] = red[0] * (1.4426f * 0.5f) / 16384.0f;
    } else {
        int i = (blockIdx.x - 1) * 256 + threadIdx.x;
        if (i < NROWS) out[524289 + i] = (float)g_idx[i];
    }
}

// ---------------------------------------------------------------- launch
extern "C" void kernel_launch(void* const* d_in, const int* in_sizes, int n_in,
                              void* d_out, int out_size) {
    const float* z  = (const float*)d_in[0];
    // d_in[1] (noise) is mathematically dead: zhat forward value == zhat_v
    const float* cb = (const float*)d_in[2];
    float* out = (float*)d_out;

    cudaFuncSetAttribute(vq_kernel, cudaFuncAttributeMaxDynamicSharedMemorySize, 131072);

    prep_kernel<<<2048, 256>>>(z);
    cb_kernel<<<2048, 256>>>(cb);
    vq_kernel<<<128, 256, 131072>>>();
    gather_kernel<<<2048, 256>>>(cb, out);
    final_small<<<65, 256>>>(out);
}